// round 13
// baseline (speedup 1.0000x reference)
#include <cuda_runtime.h>
#include <cuda_fp16.h>
#include <cstdint>

// N = 100000, E = 1,600,000, F_IN = 256, F_OUT = 128
// d_in: X [N*256] f32, edge_rows [E] i32, edge_cols [E] i32, edge_vals [E] f32,
//       W [128*256] f32, b [128] f32.  d_out: [N*128] f32.

#define F_IN   256
#define F_OUT  128
#define MAX_N  100000
#define MAX_E  1600000

// -------------------- device scratch (no allocs allowed) --------------------
__device__ __half2 g_th[(size_t)MAX_N * (F_OUT / 2)];   // transformed, fp16 (25.6 MB)
__device__ int   g_counts[MAX_N];     // zero at module load; gather re-zeros each run
__device__ int   g_offsets[MAX_N];
__device__ int   g_chunksums[256];
__device__ int2  g_sorted[MAX_E];

// ============================================================================
// Phase 1: TF32 tensor-core GEMM — occupancy-focused variant.
//   512 threads (16 warps, 4x4 grid), warp tile 32x32, accum 32 regs/thread,
//   __launch_bounds__(512,2) -> 32 warps/SM (2x previous).
//   Block tile 128x128, BK=32, 2-stage cp.async for X, LDG->reg->STS for W.
//   Dynamic smem 73.7KB/CTA.
// ============================================================================
#define BM 128
#define BK 32
#define BKP 36                       // padded smem row stride (floats)
#define XTILE (BM * BKP)             // 4608 floats per operand stage
#define GEMM_SMEM (4 * XTILE * 4)    // 2 stages x (X + W) = 73728 B

__device__ __forceinline__ float to_tf32(float f) {
    unsigned u;
    asm("cvt.rna.tf32.f32 %0, %1;" : "=r"(u) : "f"(f));
    return __uint_as_float(u);
}

__device__ __forceinline__ void cp_async16(float* smem_dst, const float* gsrc, bool valid) {
    unsigned s = (unsigned)__cvta_generic_to_shared(smem_dst);
    int sz = valid ? 16 : 0;
    asm volatile("cp.async.cg.shared.global [%0], [%1], 16, %2;\n"
                 :: "r"(s), "l"(gsrc), "r"(sz));
}

__device__ __forceinline__ void mma_tf32(
    float& c0, float& c1, float& c2, float& c3,
    unsigned a0, unsigned a1, unsigned a2, unsigned a3,
    unsigned b0, unsigned b1)
{
    asm volatile(
        "mma.sync.aligned.m16n8k8.row.col.f32.tf32.tf32.f32 "
        "{%0,%1,%2,%3}, {%4,%5,%6,%7}, {%8,%9}, {%0,%1,%2,%3};"
        : "+f"(c0), "+f"(c1), "+f"(c2), "+f"(c3)
        : "r"(a0), "r"(a1), "r"(a2), "r"(a3), "r"(b0), "r"(b1));
}

__global__ __launch_bounds__(512, 2) void gemm_tf32_kernel(
    const float* __restrict__ X,
    const float* __restrict__ W,
    const float* __restrict__ bias,
    int M)
{
    extern __shared__ __align__(16) float smem[];
    // layout: Xs[2][XTILE], Ws[2][XTILE]
    float* Xs = smem;
    float* Wsm = smem + 2 * XTILE;

    const int tid    = threadIdx.x;
    const int wid    = tid >> 5;
    const int lane   = tid & 31;
    const int warp_m = wid & 3;     // 4 warps x 32 rows
    const int warp_n = wid >> 2;    // 4 warps x 32 cols
    const int g4     = lane >> 2;
    const int tig    = lane & 3;
    const int m0     = blockIdx.x * BM;

    // loader mapping: 512 threads; thread -> (row, 8-float k chunk)
    const int lrow = tid >> 2;              // 0..127
    const int lkb  = (tid & 3) << 3;        // 0,8,16,24
    const int mrow = m0 + lrow;
    const bool mvalid = (mrow < M);
    const float* xrow = X + (size_t)(mvalid ? mrow : 0) * F_IN + lkb;
    const float* wrow = W + (size_t)lrow * F_IN + lkb;
    float* xdst = Xs + lrow * BKP + lkb;
    float* wdst = Wsm + lrow * BKP + lkb;

    float c[2][4][4];
#pragma unroll
    for (int mt = 0; mt < 2; ++mt)
#pragma unroll
        for (int nt = 0; nt < 4; ++nt)
#pragma unroll
            for (int i = 0; i < 4; ++i) c[mt][nt][i] = 0.0f;

    float wreg[8];

    // ---- prologue: stage 0 ----
#pragma unroll
    for (int i = 0; i < 2; ++i)
        cp_async16(xdst + i * 4, xrow + i * 4, mvalid);
    asm volatile("cp.async.commit_group;\n" ::: "memory");
    {
        *(float4*)&wreg[0] = *(const float4*)(wrow + 0);
        *(float4*)&wreg[4] = *(const float4*)(wrow + 4);
#pragma unroll
        for (int i = 0; i < 8; ++i) wdst[i] = to_tf32(wreg[i]);
    }
    asm volatile("cp.async.wait_group 0;\n" ::: "memory");
    __syncthreads();

    const int NITER = F_IN / BK;   // 8
#pragma unroll
    for (int it = 0; it < NITER; ++it) {
        const int buf = it & 1;
        const int nxt = buf ^ 1;

        if (it + 1 < NITER) {
            const int k1 = (it + 1) * BK;
#pragma unroll
            for (int i = 0; i < 2; ++i)
                cp_async16(xdst + nxt * XTILE + i * 4, xrow + k1 + i * 4, mvalid);
            asm volatile("cp.async.commit_group;\n" ::: "memory");
            *(float4*)&wreg[0] = *(const float4*)(wrow + k1 + 0);
            *(float4*)&wreg[4] = *(const float4*)(wrow + k1 + 4);
        }

        // ---- compute: 4 k-groups of 8 ----
        const float* Xb = Xs + buf * XTILE;
        const float* Wb = Wsm + buf * XTILE;
#pragma unroll
        for (int g = 0; g < 4; ++g) {
            const int kc = (g << 3) + tig;
            unsigned b0[4], b1[4];
#pragma unroll
            for (int nt = 0; nt < 4; ++nt) {
                const int n = warp_n * 32 + nt * 8 + g4;
                b0[nt] = __float_as_uint(Wb[n * BKP + kc]);
                b1[nt] = __float_as_uint(Wb[n * BKP + kc + 4]);
            }
#pragma unroll
            for (int mt = 0; mt < 2; ++mt) {
                const int r = warp_m * 32 + mt * 16 + g4;
                const unsigned a0 = __float_as_uint(Xb[r * BKP + kc]);
                const unsigned a1 = __float_as_uint(Xb[(r + 8) * BKP + kc]);
                const unsigned a2 = __float_as_uint(Xb[r * BKP + kc + 4]);
                const unsigned a3 = __float_as_uint(Xb[(r + 8) * BKP + kc + 4]);
#pragma unroll
                for (int nt = 0; nt < 4; ++nt)
                    mma_tf32(c[mt][nt][0], c[mt][nt][1], c[mt][nt][2], c[mt][nt][3],
                             a0, a1, a2, a3, b0[nt], b1[nt]);
            }
        }

        if (it + 1 < NITER) {
#pragma unroll
            for (int i = 0; i < 8; ++i) wdst[nxt * XTILE + i] = to_tf32(wreg[i]);
            asm volatile("cp.async.wait_group 0;\n" ::: "memory");
            __syncthreads();
        }
    }

    // ---- epilogue: bias + fp16 store ----
#pragma unroll
    for (int nt = 0; nt < 4; ++nt) {
        const int col = warp_n * 32 + nt * 8 + tig * 2;
        const float bx = bias[col], by = bias[col + 1];
#pragma unroll
        for (int mt = 0; mt < 2; ++mt) {
            const int row = m0 + warp_m * 32 + mt * 16 + g4;
            if (row < M) {
                g_th[(size_t)row * (F_OUT / 2) + (col >> 1)] =
                    __floats2half2_rn(c[mt][nt][0] + bx, c[mt][nt][1] + by);
            }
            if (row + 8 < M) {
                g_th[(size_t)(row + 8) * (F_OUT / 2) + (col >> 1)] =
                    __floats2half2_rn(c[mt][nt][2] + bx, c[mt][nt][3] + by);
            }
        }
    }
}

// ============================================================================
// Phase 2: CSR build + gather
// ============================================================================
__global__ void hist_kernel(const int* __restrict__ rows, int E) {
    int e = (blockIdx.x * blockDim.x + threadIdx.x) * 4;
    if (e + 3 < E) {
        const int4 r = *(const int4*)(rows + e);
        atomicAdd(&g_counts[r.x], 1);
        atomicAdd(&g_counts[r.y], 1);
        atomicAdd(&g_counts[r.z], 1);
        atomicAdd(&g_counts[r.w], 1);
    } else {
        for (; e < E; ++e) atomicAdd(&g_counts[rows[e]], 1);
    }
}

__global__ __launch_bounds__(1024) void scan1_kernel(int n) {
    __shared__ int wsum[32];
    const int t   = threadIdx.x;
    const int gid = blockIdx.x * 1024 + t;
    const int v   = (gid < n) ? g_counts[gid] : 0;

    int x = v;
#pragma unroll
    for (int d = 1; d < 32; d <<= 1) {
        int y = __shfl_up_sync(0xffffffffu, x, d);
        if ((t & 31) >= d) x += y;
    }
    if ((t & 31) == 31) wsum[t >> 5] = x;
    __syncthreads();
    if (t < 32) {
        int s = wsum[t];
#pragma unroll
        for (int d = 1; d < 32; d <<= 1) {
            int y = __shfl_up_sync(0xffffffffu, s, d);
            if (t >= d) s += y;
        }
        wsum[t] = s;
    }
    __syncthreads();
    const int base = (t >= 32) ? wsum[(t >> 5) - 1] : 0;
    const int incl = x + base;
    if (gid < n) g_offsets[gid] = incl - v;
    if (t == 1023) g_chunksums[blockIdx.x] = incl;
}

__global__ __launch_bounds__(128) void scan2_kernel(int nchunks) {
    __shared__ int wsum[4];
    const int t = threadIdx.x;
    const int v = (t < nchunks) ? g_chunksums[t] : 0;

    int x = v;
#pragma unroll
    for (int d = 1; d < 32; d <<= 1) {
        int y = __shfl_up_sync(0xffffffffu, x, d);
        if ((t & 31) >= d) x += y;
    }
    if ((t & 31) == 31) wsum[t >> 5] = x;
    __syncthreads();
    int base = 0;
    if ((t >> 5) > 0) base = wsum[0];
    if ((t >> 5) > 1) base += wsum[1];
    if ((t >> 5) > 2) base += wsum[2];
    if (t < nchunks) g_chunksums[t] = x + base - v;
}

__global__ void fill_kernel(const int* __restrict__ rows,
                            const int* __restrict__ cols,
                            const float* __restrict__ vals, int E) {
    int e = (blockIdx.x * blockDim.x + threadIdx.x) * 2;
    if (e + 1 < E) {
        const int2   r = *(const int2*)(rows + e);
        const int2   c = *(const int2*)(cols + e);
        const float2 v = *(const float2*)(vals + e);
        const int p0 = atomicAdd(&g_offsets[r.x], 1);
        const int p1 = atomicAdd(&g_offsets[r.y], 1);
        g_sorted[p0 + g_chunksums[r.x >> 10]] = make_int2(c.x, __float_as_int(v.x));
        g_sorted[p1 + g_chunksums[r.y >> 10]] = make_int2(c.y, __float_as_int(v.y));
    } else if (e < E) {
        const int r = rows[e];
        const int pos = atomicAdd(&g_offsets[r], 1) + g_chunksums[r >> 10];
        g_sorted[pos] = make_int2(cols[e], __float_as_int(vals[e]));
    }
}

// One warp = TWO output rows (16 lanes each, uint4 = 8 halves per lane).
// Halves the LDG instruction count per edge. Per-column accumulation order
// over edges is unchanged -> bit-identical results.
// Also resets g_counts[row] = 0 for the next graph replay.
__global__ __launch_bounds__(256) void gather_kernel(float* __restrict__ out, int N) {
    const int warp  = (int)((blockIdx.x * (unsigned)blockDim.x + threadIdx.x) >> 5);
    const int lane  = threadIdx.x & 31;
    const int half  = lane >> 4;          // 0 or 1
    const int hl    = lane & 15;          // lane within half
    const int row   = warp * 2 + half;
    if (row >= N) return;                 // N even (100000) -> uniform per warp

    const int cnt = g_counts[row];
    const int end = g_offsets[row] + g_chunksums[row >> 10];
    int i = end - cnt;
    if (hl == 0) g_counts[row] = 0;       // restore invariant for replay

    float acc[8];
#pragma unroll
    for (int j = 0; j < 8; ++j) acc[j] = 0.0f;

    // each half-warp walks its own edge list; one data LDG.128 + one meta
    // LDG.64 instruction serves both halves per iteration.
    for (; i < end; ++i) {
        const int2 e = g_sorted[i];       // broadcast within half
        const uint4 r4 = *((const uint4*)(g_th + (size_t)e.x * (F_OUT / 2)) + hl);
        const float v = __int_as_float(e.y);
        const float2 f0 = __half22float2(*(const __half2*)&r4.x);
        const float2 f1 = __half22float2(*(const __half2*)&r4.y);
        const float2 f2 = __half22float2(*(const __half2*)&r4.z);
        const float2 f3 = __half22float2(*(const __half2*)&r4.w);
        acc[0] = fmaf(v, f0.x, acc[0]); acc[1] = fmaf(v, f0.y, acc[1]);
        acc[2] = fmaf(v, f1.x, acc[2]); acc[3] = fmaf(v, f1.y, acc[3]);
        acc[4] = fmaf(v, f2.x, acc[4]); acc[5] = fmaf(v, f2.y, acc[5]);
        acc[6] = fmaf(v, f3.x, acc[6]); acc[7] = fmaf(v, f3.y, acc[7]);
    }

    float4* dst = (float4*)(out + (size_t)row * F_OUT + hl * 8);
    dst[0] = make_float4(acc[0], acc[1], acc[2], acc[3]);
    dst[1] = make_float4(acc[4], acc[5], acc[6], acc[7]);
}

// ============================================================================
// Launch: GEMM on side stream || CSR chain on capture stream; join; gather.
// ============================================================================
extern "C" void kernel_launch(void* const* d_in, const int* in_sizes, int n_in,
                              void* d_out, int out_size)
{
    const float* X    = (const float*)d_in[0];
    const int*   er   = (const int*)  d_in[1];
    const int*   ec   = (const int*)  d_in[2];
    const float* ev   = (const float*)d_in[3];
    const float* W    = (const float*)d_in[4];
    const float* bias = (const float*)d_in[5];
    float* out = (float*)d_out;

    const int M = in_sizes[0] / F_IN;   // 100000
    const int E = in_sizes[1];          // 1600000
    const int nchunks = (M + 1023) / 1024;

    static cudaStream_t s2 = nullptr;
    static cudaEvent_t  ev_fork = nullptr, ev_join = nullptr;
    if (s2 == nullptr) {
        cudaStreamCreateWithFlags(&s2, cudaStreamNonBlocking);
        cudaEventCreateWithFlags(&ev_fork, cudaEventDisableTiming);
        cudaEventCreateWithFlags(&ev_join, cudaEventDisableTiming);
        cudaFuncSetAttribute(gemm_tf32_kernel,
                             cudaFuncAttributeMaxDynamicSharedMemorySize, GEMM_SMEM);
    }

    // ---- fork ----
    cudaEventRecord(ev_fork, 0);
    cudaStreamWaitEvent(s2, ev_fork, 0);

    // g_counts is zero here (module load on first call; gather re-zeroed it
    // on every prior call) -> no memset node needed.
    hist_kernel<<<(E / 4 + 255) / 256, 256, 0, 0>>>(er, E);
    scan1_kernel<<<nchunks, 1024, 0, 0>>>(M);

    gemm_tf32_kernel<<<(M + BM - 1) / BM, 512, GEMM_SMEM, s2>>>(X, W, bias, M);

    scan2_kernel<<<1, 128, 0, 0>>>(nchunks);
    fill_kernel<<<(E / 2 + 255) / 256, 256, 0, 0>>>(er, ec, ev, E);

    // ---- join ----
    cudaEventRecord(ev_join, s2);
    cudaStreamWaitEvent(0, ev_join, 0);

    // one warp per 2 rows -> N/2 warps
    const int gwarps = (M + 1) / 2;
    gather_kernel<<<(gwarps * 32 + 255) / 256, 256, 0, 0>>>(out, M);
}